// round 1
// baseline (speedup 1.0000x reference)
#include <cuda_runtime.h>
#include <math.h>

// Problem constants
#define TOKENS 4096      // B*S = 2*2048
#define DDIM   1024
#define FDIM   4096
#define NEXP   8
#define KSLOT  2
#define PAIRS  (TOKENS * KSLOT)
#define CAP    TOKENS    // max tokens per expert (each token contributes each expert <=1)

// ---------------- scratch (__device__ globals; no allocation allowed) -------
__device__ int   g_counts[NEXP];
__device__ int   g_list[NEXP * CAP];       // pair index p = t*2 + k, grouped by expert
__device__ float g_prob[PAIRS];            // routing prob per pair
__device__ float g_h[(size_t)PAIRS * FDIM]; // layer-1 activations (134 MB)

// ---------------- helpers ---------------------------------------------------
__device__ __forceinline__ float gelu_tanh(float v) {
    // jax.nn.gelu default (approximate=True)
    const float c = 0.7978845608028654f;   // sqrt(2/pi)
    float u = c * (v + 0.044715f * v * v * v);
    return 0.5f * v * (1.0f + tanhf(u));
}

// ---------------- kernel 0: zero output + counts -----------------------------
__global__ void zero_kernel(float* __restrict__ out, int n) {
    int i = blockIdx.x * blockDim.x + threadIdx.x;
    if (i < n) out[i] = 0.0f;
    if (blockIdx.x == 0 && threadIdx.x < NEXP) g_counts[threadIdx.x] = 0;
}

// ---------------- kernel 1: gate (logits -> softmax -> top2 -> route) --------
__global__ __launch_bounds__(256) void gate_kernel(
    const float* __restrict__ x, const float* __restrict__ gw)
{
    int t = blockIdx.x;
    const float* xr = x + (size_t)t * DDIM;

    float acc[NEXP];
#pragma unroll
    for (int e = 0; e < NEXP; e++) acc[e] = 0.0f;

    for (int d = threadIdx.x; d < DDIM; d += 256) {
        float xv = xr[d];
#pragma unroll
        for (int e = 0; e < NEXP; e++) acc[e] += xv * gw[e * DDIM + d];
    }
    // warp reduce
#pragma unroll
    for (int e = 0; e < NEXP; e++) {
#pragma unroll
        for (int o = 16; o > 0; o >>= 1)
            acc[e] += __shfl_xor_sync(0xffffffff, acc[e], o);
    }
    __shared__ float red[NEXP][8];
    int warp = threadIdx.x >> 5, lane = threadIdx.x & 31;
    if (lane == 0) {
#pragma unroll
        for (int e = 0; e < NEXP; e++) red[e][warp] = acc[e];
    }
    __syncthreads();

    if (threadIdx.x == 0) {
        float lg[NEXP];
#pragma unroll
        for (int e = 0; e < NEXP; e++) {
            float s = 0.0f;
#pragma unroll
            for (int w = 0; w < 8; w++) s += red[e][w];
            lg[e] = s;
        }
        // softmax over 8
        float mx = lg[0];
#pragma unroll
        for (int e = 1; e < NEXP; e++) mx = fmaxf(mx, lg[e]);
        float pe[NEXP], s = 0.0f;
#pragma unroll
        for (int e = 0; e < NEXP; e++) { pe[e] = expf(lg[e] - mx); s += pe[e]; }
        float inv = 1.0f / s;
        // top-2 (strict > keeps lowest index on ties, matching top_k)
        int i0 = 0;
#pragma unroll
        for (int e = 1; e < NEXP; e++) if (pe[e] > pe[i0]) i0 = e;
        int i1 = (i0 == 0) ? 1 : 0;
#pragma unroll
        for (int e = 0; e < NEXP; e++)
            if (e != i0 && pe[e] > pe[i1]) i1 = e;

        int p0 = t * 2, p1 = t * 2 + 1;
        g_prob[p0] = pe[i0] * inv;
        g_prob[p1] = pe[i1] * inv;
        int pos0 = atomicAdd(&g_counts[i0], 1);
        g_list[i0 * CAP + pos0] = p0;
        int pos1 = atomicAdd(&g_counts[i1], 1);
        g_list[i1 * CAP + pos1] = p1;
    }
}

// ---------------- kernel 2/3: grouped SGEMM 128x128x8, fp32 ------------------
// C[m,n] = sum_k A[row(m), k] * W[(n*E + e)*KDIM + k]
// Layer1 (L2TAG=false): A=x (row=pair>>1), fused bias+gelu -> g_h[pair]
// Layer2 (L2TAG=true):  A=g_h (row=pair),  fused bias, *prob, atomicAdd -> out
template <int KDIM, bool L2TAG>
__global__ __launch_bounds__(256) void moe_gemm(
    const float* __restrict__ Ain,
    const float* __restrict__ W,
    const float* __restrict__ bias,
    float* __restrict__ dout)
{
    int e   = blockIdx.z;
    int cnt = g_counts[e];
    int m0  = blockIdx.y * 128;
    if (m0 >= cnt) return;
    int n0  = blockIdx.x * 128;

    __shared__ __align__(16) float As[8][128];
    __shared__ __align__(16) float Bs[8][128];
    __shared__ int rows[128];

    int tid = threadIdx.x;
    if (tid < 128) {
        int m = m0 + tid;
        rows[tid] = g_list[e * CAP + (m < cnt ? m : m0)];
    }
    __syncthreads();

    // loader mapping: 2 threads per row, float4 each -> 128 rows x 8 k
    int am = tid >> 1;
    int ak = (tid & 1) << 2;
    int bn = tid >> 1;
    int bk = (tid & 1) << 2;

    int pa = rows[am];
    const float* Abase = L2TAG ? (const float*)g_h : Ain;
    const float* Arow  = Abase + (size_t)(L2TAG ? pa : (pa >> 1)) * KDIM;
    const float* Wrow  = W + ((size_t)(n0 + bn) * NEXP + e) * KDIM;

    // compute mapping: 16x16 threads, 8x8 each
    int tm = (tid >> 4) << 3;
    int tn = (tid & 15) << 3;

    float acc[8][8];
#pragma unroll
    for (int i = 0; i < 8; i++)
#pragma unroll
        for (int j = 0; j < 8; j++) acc[i][j] = 0.0f;

    for (int k0 = 0; k0 < KDIM; k0 += 8) {
        float4 av = *(const float4*)(Arow + k0 + ak);
        float4 bv = *(const float4*)(Wrow + k0 + bk);
        __syncthreads();
        As[ak + 0][am] = av.x; As[ak + 1][am] = av.y;
        As[ak + 2][am] = av.z; As[ak + 3][am] = av.w;
        Bs[bk + 0][bn] = bv.x; Bs[bk + 1][bn] = bv.y;
        Bs[bk + 2][bn] = bv.z; Bs[bk + 3][bn] = bv.w;
        __syncthreads();
#pragma unroll
        for (int kk = 0; kk < 8; kk++) {
            float a[8], b[8];
            *(float4*)(a)     = *(const float4*)(&As[kk][tm]);
            *(float4*)(a + 4) = *(const float4*)(&As[kk][tm + 4]);
            *(float4*)(b)     = *(const float4*)(&Bs[kk][tn]);
            *(float4*)(b + 4) = *(const float4*)(&Bs[kk][tn + 4]);
#pragma unroll
            for (int i = 0; i < 8; i++)
#pragma unroll
                for (int j = 0; j < 8; j++)
                    acc[i][j] += a[i] * b[j];
        }
    }

    // epilogue
#pragma unroll
    for (int i = 0; i < 8; i++) {
        int m = tm + i;
        if (m0 + m >= cnt) break;
        int p = rows[m];
        if (!L2TAG) {
            float* hp = g_h + (size_t)p * FDIM + n0 + tn;
            const float* bb = bias + e * FDIM + n0 + tn;
#pragma unroll
            for (int j = 0; j < 8; j++)
                hp[j] = gelu_tanh(acc[i][j] + bb[j]);
        } else {
            float pr = g_prob[p];
            float* op = dout + (size_t)(p >> 1) * DDIM + n0 + tn;
            const float* bb = bias + e * DDIM + n0 + tn;
#pragma unroll
            for (int j = 0; j < 8; j++)
                atomicAdd(&op[j], pr * (acc[i][j] + bb[j]));
        }
    }
}

// ---------------- launch ------------------------------------------------------
extern "C" void kernel_launch(void* const* d_in, const int* in_sizes, int n_in,
                              void* d_out, int out_size)
{
    (void)in_sizes; (void)n_in; (void)out_size;
    const float* x  = (const float*)d_in[0];
    const float* gw = (const float*)d_in[1];
    const float* w1 = (const float*)d_in[2];
    const float* b1 = (const float*)d_in[3];
    const float* w2 = (const float*)d_in[4];
    const float* b2 = (const float*)d_in[5];
    float* out = (float*)d_out;

    zero_kernel<<<(TOKENS * DDIM + 255) / 256, 256>>>(out, TOKENS * DDIM);
    gate_kernel<<<TOKENS, 256>>>(x, gw);

    dim3 g1(FDIM / 128, TOKENS / 128, NEXP);   // 32 x 32 x 8
    moe_gemm<DDIM, false><<<g1, 256>>>(x, w1, b1, nullptr);

    dim3 g2(DDIM / 128, TOKENS / 128, NEXP);   // 8 x 32 x 8
    moe_gemm<FDIM, true><<<g2, 256>>>(nullptr, w2, b2, out);
}

// round 2
// speedup vs baseline: 2.4664x; 2.4664x over previous
#include <cuda_runtime.h>
#include <cuda_bf16.h>
#include <math.h>
#include <stdint.h>

// Problem constants
#define TOKENS 4096      // B*S
#define DDIM   1024
#define FDIM   4096
#define NEXP   8
#define PAIRS  (TOKENS * 2)
#define CAP    TOKENS

// GEMM tiling
#define BM 128
#define BN 128
#define BK 32
#define LDT 40           // padded smem stride (bf16 elems) -> 80B rows, ldmatrix conflict-free

// ---------------- scratch ----------------------------------------------------
__device__ int   g_counts[NEXP];
__device__ int   g_list[NEXP * CAP];
__device__ float g_prob[PAIRS];
__device__ float g_h[(size_t)PAIRS * FDIM];   // layer-1 activations, fp32

// ---------------- helpers ----------------------------------------------------
__device__ __forceinline__ float gelu_tanh(float v) {
    const float c = 0.7978845608028654f;
    float u = c * (v + 0.044715f * v * v * v);
    return 0.5f * v * (1.0f + tanhf(u));
}

__device__ __forceinline__ uint32_t pack_bf2(float a, float b) {
    __nv_bfloat162 t = __floats2bfloat162_rn(a, b);
    return *reinterpret_cast<uint32_t*>(&t);
}

// split float4 into hi/lo bf16 pairs, store 8B each
__device__ __forceinline__ void sts_split(__nv_bfloat16* H, __nv_bfloat16* L,
                                          int off, float4 v) {
    float hx = __bfloat162float(__float2bfloat16_rn(v.x));
    float hy = __bfloat162float(__float2bfloat16_rn(v.y));
    float hz = __bfloat162float(__float2bfloat16_rn(v.z));
    float hw = __bfloat162float(__float2bfloat16_rn(v.w));
    uint2 hv = make_uint2(pack_bf2(hx, hy), pack_bf2(hz, hw));
    uint2 lv = make_uint2(pack_bf2(v.x - hx, v.y - hy), pack_bf2(v.z - hz, v.w - hw));
    *reinterpret_cast<uint2*>(H + off) = hv;
    *reinterpret_cast<uint2*>(L + off) = lv;
}

__device__ __forceinline__ void ldm_x4(uint32_t* r, const __nv_bfloat16* p) {
    uint32_t a = (uint32_t)__cvta_generic_to_shared(p);
    asm volatile("ldmatrix.sync.aligned.m8n8.x4.shared.b16 {%0,%1,%2,%3}, [%4];"
                 : "=r"(r[0]), "=r"(r[1]), "=r"(r[2]), "=r"(r[3]) : "r"(a));
}

__device__ __forceinline__ void mma16816(float* c, const uint32_t* a, const uint32_t* b) {
    asm volatile(
        "mma.sync.aligned.m16n8k16.row.col.f32.bf16.bf16.f32 "
        "{%0,%1,%2,%3}, {%4,%5,%6,%7}, {%8,%9}, {%0,%1,%2,%3};"
        : "+f"(c[0]), "+f"(c[1]), "+f"(c[2]), "+f"(c[3])
        : "r"(a[0]), "r"(a[1]), "r"(a[2]), "r"(a[3]), "r"(b[0]), "r"(b[1]));
}

// ---------------- kernel 0: zero output + counts ------------------------------
__global__ void zero_kernel(float* __restrict__ out, int n) {
    int i = blockIdx.x * blockDim.x + threadIdx.x;
    if (i < n) out[i] = 0.0f;
    if (blockIdx.x == 0 && threadIdx.x < NEXP) g_counts[threadIdx.x] = 0;
}

// ---------------- kernel 1: gate ---------------------------------------------
__global__ __launch_bounds__(256) void gate_kernel(
    const float* __restrict__ x, const float* __restrict__ gw)
{
    int t = blockIdx.x;
    const float* xr = x + (size_t)t * DDIM;

    float acc[NEXP];
#pragma unroll
    for (int e = 0; e < NEXP; e++) acc[e] = 0.0f;

    for (int d = threadIdx.x; d < DDIM; d += 256) {
        float xv = xr[d];
#pragma unroll
        for (int e = 0; e < NEXP; e++) acc[e] += xv * gw[e * DDIM + d];
    }
#pragma unroll
    for (int e = 0; e < NEXP; e++) {
#pragma unroll
        for (int o = 16; o > 0; o >>= 1)
            acc[e] += __shfl_xor_sync(0xffffffff, acc[e], o);
    }
    __shared__ float red[NEXP][8];
    int warp = threadIdx.x >> 5, lane = threadIdx.x & 31;
    if (lane == 0) {
#pragma unroll
        for (int e = 0; e < NEXP; e++) red[e][warp] = acc[e];
    }
    __syncthreads();

    if (threadIdx.x == 0) {
        float lg[NEXP];
#pragma unroll
        for (int e = 0; e < NEXP; e++) {
            float s = 0.0f;
#pragma unroll
            for (int w = 0; w < 8; w++) s += red[e][w];
            lg[e] = s;
        }
        float mx = lg[0];
#pragma unroll
        for (int e = 1; e < NEXP; e++) mx = fmaxf(mx, lg[e]);
        float pe[NEXP], s = 0.0f;
#pragma unroll
        for (int e = 0; e < NEXP; e++) { pe[e] = expf(lg[e] - mx); s += pe[e]; }
        float inv = 1.0f / s;
        int i0 = 0;
#pragma unroll
        for (int e = 1; e < NEXP; e++) if (pe[e] > pe[i0]) i0 = e;
        int i1 = (i0 == 0) ? 1 : 0;
#pragma unroll
        for (int e = 0; e < NEXP; e++)
            if (e != i0 && pe[e] > pe[i1]) i1 = e;

        int p0 = t * 2, p1 = t * 2 + 1;
        g_prob[p0] = pe[i0] * inv;
        g_prob[p1] = pe[i1] * inv;
        int pos0 = atomicAdd(&g_counts[i0], 1);
        g_list[i0 * CAP + pos0] = p0;
        int pos1 = atomicAdd(&g_counts[i1], 1);
        g_list[i1 * CAP + pos1] = p1;
    }
}

// ---------------- grouped GEMM with bf16x3 tensor-core emulation --------------
// C[m,n] = sum_k A[row(m),k] * W[(n*E+e)*KDIM + k], fp32-accurate via
// acc += Ah*Bh + Ah*Bl + Al*Bh  (hi/lo bf16 split done at smem staging)
template <int KDIM, bool L2TAG>
__global__ __launch_bounds__(256, 1) void moe_mma(
    const float* __restrict__ Ain,
    const float* __restrict__ W,
    const float* __restrict__ bias,
    float* __restrict__ dout)
{
    int e   = blockIdx.z;
    int cnt = g_counts[e];
    int m0  = blockIdx.y * BM;
    if (m0 >= cnt) return;
    int n0  = blockIdx.x * BN;

    __shared__ __align__(16) __nv_bfloat16 Ah[BM * LDT], Al[BM * LDT];
    __shared__ __align__(16) __nv_bfloat16 Bh[BN * LDT], Bl[BN * LDT];
    __shared__ int rows[BM];

    int tid = threadIdx.x;
    if (tid < BM) {
        int m = m0 + tid;
        rows[tid] = g_list[e * CAP + (m < cnt ? m : m0)];
    }
    __syncthreads();

    // ---- staging pointers: 4 slots each for A and B ----
    const float* Abase = L2TAG ? (const float*)g_h : Ain;
    const float* aptr[4];
    const float* bptr[4];
    int soff[4];
#pragma unroll
    for (int i = 0; i < 4; i++) {
        int s  = tid + i * 256;
        int r  = s >> 3;
        int k4 = (s & 7) << 2;
        int p  = rows[r];
        size_t arow = L2TAG ? (size_t)p : (size_t)(p >> 1);
        aptr[i] = Abase + arow * KDIM + k4;
        bptr[i] = W + ((size_t)(n0 + r) * NEXP + e) * KDIM + k4;
        soff[i] = r * LDT + k4;
    }

    float4 areg[4], breg[4];
#pragma unroll
    for (int i = 0; i < 4; i++) {
        areg[i] = *(const float4*)(aptr[i]);
        breg[i] = *(const float4*)(bptr[i]);
    }

    // ---- warp tiling: 2(m) x 4(n) warps; warp tile 64x32 ----
    int w  = tid >> 5;
    int wm = w & 1;
    int wn = w >> 1;
    int l  = tid & 31;
    int li = l >> 3, lr = l & 7;   // ldmatrix lane addressing

    float acc[4][4][4];
#pragma unroll
    for (int im = 0; im < 4; im++)
#pragma unroll
        for (int in = 0; in < 4; in++)
#pragma unroll
            for (int q = 0; q < 4; q++) acc[im][in][q] = 0.0f;

    for (int k0 = 0; ; ) {
        __syncthreads();
#pragma unroll
        for (int i = 0; i < 4; i++) {
            sts_split(Ah, Al, soff[i], areg[i]);
            sts_split(Bh, Bl, soff[i], breg[i]);
        }
        __syncthreads();

        k0 += BK;
        bool more = (k0 < KDIM);
        if (more) {
#pragma unroll
            for (int i = 0; i < 4; i++) {
                areg[i] = *(const float4*)(aptr[i] + k0);
                breg[i] = *(const float4*)(bptr[i] + k0);
            }
        }

        // compute 2 k-chunks of 16
#pragma unroll
        for (int kk = 0; kk < BK; kk += 16) {
            uint32_t afh[4][4], afl[4][4], bfh[4][2], bfl[4][2];
#pragma unroll
            for (int im = 0; im < 4; im++) {
                int arow = wm * 64 + im * 16 + lr + (li & 1) * 8;
                int acol = kk + (li >> 1) * 8;
                ldm_x4(afh[im], &Ah[arow * LDT + acol]);
                ldm_x4(afl[im], &Al[arow * LDT + acol]);
            }
#pragma unroll
            for (int h = 0; h < 2; h++) {
                int nrow = wn * 32 + h * 16 + (li >> 1) * 8 + lr;
                int ncol = kk + (li & 1) * 8;
                uint32_t t4[4];
                ldm_x4(t4, &Bh[nrow * LDT + ncol]);
                bfh[2 * h][0] = t4[0]; bfh[2 * h][1] = t4[1];
                bfh[2 * h + 1][0] = t4[2]; bfh[2 * h + 1][1] = t4[3];
                ldm_x4(t4, &Bl[nrow * LDT + ncol]);
                bfl[2 * h][0] = t4[0]; bfl[2 * h][1] = t4[1];
                bfl[2 * h + 1][0] = t4[2]; bfl[2 * h + 1][1] = t4[3];
            }
#pragma unroll
            for (int im = 0; im < 4; im++)
#pragma unroll
                for (int in = 0; in < 4; in++) {
                    mma16816(acc[im][in], afh[im], bfh[in]);
                    mma16816(acc[im][in], afh[im], bfl[in]);
                    mma16816(acc[im][in], afl[im], bfh[in]);
                }
        }
        if (!more) break;
    }

    // ---- epilogue ----
    int qr = l >> 2;          // row within 8-row group
    int qc = (l & 3) * 2;     // col pair base
#pragma unroll
    for (int im = 0; im < 4; im++) {
#pragma unroll
        for (int half = 0; half < 2; half++) {
            int m_loc = wm * 64 + im * 16 + qr + half * 8;
            if (m0 + m_loc >= cnt) continue;
            int p = rows[m_loc];
            if (!L2TAG) {
                float* hp = g_h + (size_t)p * FDIM;
                const float* bb = bias + e * FDIM;
#pragma unroll
                for (int in = 0; in < 4; in++) {
                    int col = n0 + wn * 32 + in * 8 + qc;
                    float v0 = acc[im][in][half * 2 + 0] + bb[col];
                    float v1 = acc[im][in][half * 2 + 1] + bb[col + 1];
                    hp[col]     = gelu_tanh(v0);
                    hp[col + 1] = gelu_tanh(v1);
                }
            } else {
                float pr = g_prob[p];
                float* op = dout + (size_t)(p >> 1) * DDIM;
                const float* bb = bias + e * DDIM;
#pragma unroll
                for (int in = 0; in < 4; in++) {
                    int col = n0 + wn * 32 + in * 8 + qc;
                    atomicAdd(&op[col],     pr * (acc[im][in][half * 2 + 0] + bb[col]));
                    atomicAdd(&op[col + 1], pr * (acc[im][in][half * 2 + 1] + bb[col + 1]));
                }
            }
        }
    }
}

// ---------------- launch -------------------------------------------------------
extern "C" void kernel_launch(void* const* d_in, const int* in_sizes, int n_in,
                              void* d_out, int out_size)
{
    (void)in_sizes; (void)n_in; (void)out_size;
    const float* x  = (const float*)d_in[0];
    const float* gw = (const float*)d_in[1];
    const float* w1 = (const float*)d_in[2];
    const float* b1 = (const float*)d_in[3];
    const float* w2 = (const float*)d_in[4];
    const float* b2 = (const float*)d_in[5];
    float* out = (float*)d_out;

    zero_kernel<<<(TOKENS * DDIM + 255) / 256, 256>>>(out, TOKENS * DDIM);
    gate_kernel<<<TOKENS, 256>>>(x, gw);

    dim3 g1(FDIM / BN, TOKENS / BM, NEXP);   // 32 x 32 x 8
    moe_mma<DDIM, false><<<g1, 256>>>(x, w1, b1, nullptr);

    dim3 g2(DDIM / BN, TOKENS / BM, NEXP);   // 8 x 32 x 8
    moe_mma<FDIM, true><<<g2, 256>>>(nullptr, w2, b2, out);
}

// round 5
// speedup vs baseline: 3.9362x; 1.5959x over previous
#include <cuda_runtime.h>
#include <cuda_fp16.h>
#include <math.h>
#include <stdint.h>

// ---------------- problem constants -----------------------------------------
#define TOKENS 4096
#define DDIM   1024
#define FDIM   4096
#define NEXP   8
#define PAIRS  (TOKENS * 2)
#define CAP    TOKENS

// ---------------- GEMM tiling ------------------------------------------------
#define BM 128
#define BN 128
#define BK 32
#define NTH 256
#define LDT 40                         // padded smem stride (halves) = 80 B
#define A_BYTES  (BM * LDT * 2)        // 10240
#define STAGE_BYTES (3 * BM * LDT * 2) // A + Bh + Bl = 30720
#define SOFF_STAGE 1024
#define SMEM_BYTES (SOFF_STAGE + 2 * STAGE_BYTES)  // 62464

#define WSCALE 64.0f
#define WINV   (1.0f / 64.0f)

// ---------------- scratch (72 MB total — within proven budget) -----------------
__device__ int    g_counts[NEXP];
__device__ int    g_list[NEXP * CAP];
__device__ float  g_prob[PAIRS];
__device__ __half g_xf[(size_t)TOKENS * DDIM];   // fp16 x        (8 MB)
__device__ __half g_hf[(size_t)PAIRS * FDIM];    // fp16 h        (64 MB)

// ---------------- ptx helpers --------------------------------------------------
__device__ __forceinline__ uint32_t smem_u32(const void* p) {
    uint32_t a;
    asm("{ .reg .u64 t; cvta.to.shared.u64 t, %1; cvt.u32.u64 %0, t; }"
        : "=r"(a) : "l"(p));
    return a;
}
__device__ __forceinline__ void cp16(uint32_t dst, const void* src) {
    asm volatile("cp.async.cg.shared.global [%0], [%1], 16;" :: "r"(dst), "l"(src));
}
__device__ __forceinline__ void cp_commit() {
    asm volatile("cp.async.commit_group;" ::: "memory");
}
template <int N>
__device__ __forceinline__ void cp_wait() {
    asm volatile("cp.async.wait_group %0;" :: "n"(N) : "memory");
}
__device__ __forceinline__ void ldm4(uint32_t* r, uint32_t a) {
    asm volatile("ldmatrix.sync.aligned.m8n8.x4.shared.b16 {%0,%1,%2,%3}, [%4];"
                 : "=r"(r[0]), "=r"(r[1]), "=r"(r[2]), "=r"(r[3]) : "r"(a));
}
__device__ __forceinline__ void mma_f16(float* c, const uint32_t* a, const uint32_t* b) {
    asm volatile(
        "mma.sync.aligned.m16n8k16.row.col.f32.f16.f16.f32 "
        "{%0,%1,%2,%3}, {%4,%5,%6,%7}, {%8,%9}, {%0,%1,%2,%3};"
        : "+f"(c[0]), "+f"(c[1]), "+f"(c[2]), "+f"(c[3])
        : "r"(a[0]), "r"(a[1]), "r"(a[2]), "r"(a[3]), "r"(b[0]), "r"(b[1]));
}

// ---------------- math helpers --------------------------------------------------
__device__ __forceinline__ float gelu_tanh(float v) {
    const float c = 0.7978845608028654f;
    float u = c * (v + 0.044715f * v * v * v);
    return 0.5f * v * (1.0f + tanhf(u));
}

// split a scaled-by-64 float4 of W into hi/lo fp16, store 8 B each to smem
__device__ __forceinline__ void split_sts(char* smem, uint32_t offH, uint32_t offL,
                                          float4 v) {
    float s0 = WSCALE * v.x, s1 = WSCALE * v.y, s2 = WSCALE * v.z, s3 = WSCALE * v.w;
    __half h0 = __float2half_rn(s0), h1 = __float2half_rn(s1);
    __half h2 = __float2half_rn(s2), h3 = __float2half_rn(s3);
    __half2 hh0 = __halves2half2(h0, h1), hh1 = __halves2half2(h2, h3);
    __half2 ll0 = __halves2half2(__float2half_rn(s0 - __half2float(h0)),
                                 __float2half_rn(s1 - __half2float(h1)));
    __half2 ll1 = __halves2half2(__float2half_rn(s2 - __half2float(h2)),
                                 __float2half_rn(s3 - __half2float(h3)));
    *reinterpret_cast<uint2*>(smem + offH) = make_uint2(*(uint32_t*)&hh0, *(uint32_t*)&hh1);
    *reinterpret_cast<uint2*>(smem + offL) = make_uint2(*(uint32_t*)&ll0, *(uint32_t*)&ll1);
}

// ---------------- kernel 0: zero output + counts --------------------------------
__global__ void zero_kernel(float* __restrict__ out, int n) {
    int i = blockIdx.x * blockDim.x + threadIdx.x;
    if (i < n) out[i] = 0.0f;
    if (blockIdx.x == 0 && threadIdx.x < NEXP) g_counts[threadIdx.x] = 0;
}

// ---------------- prepass: x -> fp16 ---------------------------------------------
__global__ void conv_x_kernel(const float4* __restrict__ x, int n4) {
    int i = blockIdx.x * blockDim.x + threadIdx.x;
    if (i >= n4) return;
    float4 v = x[i];
    __half2 h0 = __halves2half2(__float2half_rn(v.x), __float2half_rn(v.y));
    __half2 h1 = __halves2half2(__float2half_rn(v.z), __float2half_rn(v.w));
    *reinterpret_cast<uint2*>(g_xf + (size_t)i * 4) =
        make_uint2(*(uint32_t*)&h0, *(uint32_t*)&h1);
}

// ---------------- kernel: gate -----------------------------------------------------
__global__ __launch_bounds__(256) void gate_kernel(
    const float* __restrict__ x, const float* __restrict__ gw)
{
    int t = blockIdx.x;
    const float* xr = x + (size_t)t * DDIM;

    float acc[NEXP];
#pragma unroll
    for (int e = 0; e < NEXP; e++) acc[e] = 0.0f;
    for (int d = threadIdx.x; d < DDIM; d += 256) {
        float xv = xr[d];
#pragma unroll
        for (int e = 0; e < NEXP; e++) acc[e] += xv * gw[e * DDIM + d];
    }
#pragma unroll
    for (int e = 0; e < NEXP; e++) {
#pragma unroll
        for (int o = 16; o > 0; o >>= 1)
            acc[e] += __shfl_xor_sync(0xffffffff, acc[e], o);
    }
    __shared__ float red[NEXP][8];
    int warp = threadIdx.x >> 5, lane = threadIdx.x & 31;
    if (lane == 0) {
#pragma unroll
        for (int e = 0; e < NEXP; e++) red[e][warp] = acc[e];
    }
    __syncthreads();
    if (threadIdx.x == 0) {
        float lg[NEXP];
#pragma unroll
        for (int e = 0; e < NEXP; e++) {
            float s = 0.0f;
#pragma unroll
            for (int w = 0; w < 8; w++) s += red[e][w];
            lg[e] = s;
        }
        float mx = lg[0];
#pragma unroll
        for (int e = 1; e < NEXP; e++) mx = fmaxf(mx, lg[e]);
        float pe[NEXP], s = 0.0f;
#pragma unroll
        for (int e = 0; e < NEXP; e++) { pe[e] = expf(lg[e] - mx); s += pe[e]; }
        float inv = 1.0f / s;
        int i0 = 0;
#pragma unroll
        for (int e = 1; e < NEXP; e++) if (pe[e] > pe[i0]) i0 = e;
        int i1 = (i0 == 0) ? 1 : 0;
#pragma unroll
        for (int e = 0; e < NEXP; e++)
            if (e != i0 && pe[e] > pe[i1]) i1 = e;
        int p0 = t * 2, p1 = t * 2 + 1;
        g_prob[p0] = pe[i0] * inv;
        g_prob[p1] = pe[i1] * inv;
        int pos0 = atomicAdd(&g_counts[i0], 1);
        g_list[i0 * CAP + pos0] = p0;
        int pos1 = atomicAdd(&g_counts[i1], 1);
        g_list[i1 * CAP + pos1] = p1;
    }
}

// ---------------- grouped fp16 2-pass GEMM ------------------------------------------
// C[m,n] = sum_k A[row(m),k] * (Wh+Wl)[n0+n][k]/64 ; A fp16 via cp.async,
// W fp32 LDG -> in-register split -> STS. Double-buffered smem, 1 sync/iter.
template <int KDIM, bool L2TAG>
__global__ __launch_bounds__(NTH, 2)
void moe_fp16(const float* __restrict__ W,
              const float* __restrict__ bias,
              float* __restrict__ dout)
{
    int e   = blockIdx.z;
    int cnt = g_counts[e];
    int m0  = blockIdx.y * BM;
    if (m0 >= cnt) return;
    int n0  = blockIdx.x * BN;

    extern __shared__ __align__(128) char smem[];
    uint32_t sb = smem_u32(smem);
    int* rows = (int*)smem;

    int tid = threadIdx.x, wid = tid >> 5, lane = tid & 31;

    if (tid < BM) {
        int m = m0 + tid;
        rows[tid] = g_list[e * CAP + (m < cnt ? m : m0)];
    }
    __syncthreads();

    // ---- A: cp.async mapping (2 x 16B per thread) ----
    int arow = tid >> 1;
    int pa = rows[arow];
    const __half* a_row = L2TAG ? (g_hf + (size_t)pa * KDIM)
                                : (g_xf + (size_t)(pa >> 1) * KDIM);
    const char* a_src = (const char*)a_row + (tid & 1) * 32;
    uint32_t a_dst = sb + SOFF_STAGE + (uint32_t)arow * 80 + (tid & 1) * 32;

    // ---- W: LDG float4 mapping (4 per thread) ----
    const float* wp[4];
    uint32_t woff[4];
#pragma unroll
    for (int j = 0; j < 4; j++) {
        int s = tid + j * 256;
        int r = s >> 3;
        int k4 = (s & 7) << 2;
        wp[j] = W + ((size_t)(n0 + r) * NEXP + e) * KDIM + k4;
        woff[j] = (uint32_t)r * 80 + (uint32_t)k4 * 2;
    }

    constexpr int NCH = KDIM / BK;

    // ---- fragment addressing (validated in R2) ----
    int wm = wid & 1, wn = wid >> 1;
    int li = lane >> 3, lr = lane & 7;
    uint32_t aoff = (uint32_t)((wm * 64 + lr + (li & 1) * 8) * 80 + (li >> 1) * 16);
    uint32_t boff = (uint32_t)((wn * 32 + (li >> 1) * 8 + lr) * 80 + (li & 1) * 16);

    float acc[4][4][4];
#pragma unroll
    for (int im = 0; im < 4; im++)
#pragma unroll
        for (int in = 0; in < 4; in++)
#pragma unroll
            for (int q = 0; q < 4; q++) acc[im][in][q] = 0.0f;

    // ---- prologue: A chunk0 in flight, W chunk0 in regs ----
    cp16(a_dst, a_src);
    cp16(a_dst + 16, a_src + 16);
    cp_commit();
    float4 wreg[4];
#pragma unroll
    for (int j = 0; j < 4; j++) wreg[j] = *(const float4*)(wp[j]);

    for (int i = 0; i < NCH; i++) {
        uint32_t st = sb + SOFF_STAGE + (uint32_t)(i & 1) * STAGE_BYTES;
        char* stc = smem + SOFF_STAGE + (size_t)(i & 1) * STAGE_BYTES;

        // stage W chunk i (split hi/lo)
#pragma unroll
        for (int j = 0; j < 4; j++)
            split_sts(stc, A_BYTES + woff[j], 2 * A_BYTES + woff[j], wreg[j]);

        cp_wait<0>();          // A chunk i landed
        __syncthreads();       // all staging visible; prior buffer reads done

        // issue A chunk i+1 into the other buffer
        if (i + 1 < NCH) {
            uint32_t nst = sb + SOFF_STAGE + (uint32_t)((i + 1) & 1) * STAGE_BYTES
                         + (a_dst - (sb + SOFF_STAGE));
            int kb = (i + 1) * BK * 2;
            cp16(nst, a_src + kb);
            cp16(nst + 16, a_src + kb + 16);
        }
        cp_commit();

        // prefetch W chunk i+1
        if (i + 1 < NCH) {
            int k0 = (i + 1) * BK;
#pragma unroll
            for (int j = 0; j < 4; j++) wreg[j] = *(const float4*)(wp[j] + k0);
        }

        // compute chunk i
        uint32_t As = st, Bh = st + A_BYTES, Bl = st + 2 * A_BYTES;
#pragma unroll
        for (int kk = 0; kk < BK; kk += 16) {
            uint32_t bh[4][2], bl[4][2];
#pragma unroll
            for (int h = 0; h < 2; h++) {
                uint32_t t4[4];
                ldm4(t4, Bh + boff + h * 1280 + kk * 2);
                bh[2 * h][0] = t4[0]; bh[2 * h][1] = t4[1];
                bh[2 * h + 1][0] = t4[2]; bh[2 * h + 1][1] = t4[3];
                ldm4(t4, Bl + boff + h * 1280 + kk * 2);
                bl[2 * h][0] = t4[0]; bl[2 * h][1] = t4[1];
                bl[2 * h + 1][0] = t4[2]; bl[2 * h + 1][1] = t4[3];
            }
#pragma unroll
            for (int im = 0; im < 4; im++) {
                uint32_t af[4];
                ldm4(af, As + aoff + im * 1280 + kk * 2);
#pragma unroll
                for (int in = 0; in < 4; in++) {
                    mma_f16(acc[im][in], af, bh[in]);
                    mma_f16(acc[im][in], af, bl[in]);
                }
            }
        }
    }

    // ---- epilogue ----
    int qr = lane >> 2, qc = (lane & 3) * 2;
#pragma unroll
    for (int im = 0; im < 4; im++) {
#pragma unroll
        for (int half = 0; half < 2; half++) {
            int m_loc = wm * 64 + im * 16 + qr + half * 8;
            if (m0 + m_loc >= cnt) continue;
            int p = rows[m_loc];
            if (!L2TAG) {
                __half* hp = g_hf + (size_t)p * FDIM;
                const float* bb = bias + (size_t)e * FDIM;
#pragma unroll
                for (int in = 0; in < 4; in++) {
                    int col = n0 + wn * 32 + in * 8 + qc;
                    float v0 = acc[im][in][half * 2 + 0] * WINV + bb[col];
                    float v1 = acc[im][in][half * 2 + 1] * WINV + bb[col + 1];
                    __half2 hv = __halves2half2(__float2half_rn(gelu_tanh(v0)),
                                                __float2half_rn(gelu_tanh(v1)));
                    *reinterpret_cast<uint32_t*>(hp + col) = *(uint32_t*)&hv;
                }
            } else {
                float pr = g_prob[p];
                float* op = dout + (size_t)(p >> 1) * DDIM;
                const float* bb = bias + (size_t)e * DDIM;
#pragma unroll
                for (int in = 0; in < 4; in++) {
                    int col = n0 + wn * 32 + in * 8 + qc;
                    atomicAdd(&op[col],
                              pr * (acc[im][in][half * 2 + 0] * WINV + bb[col]));
                    atomicAdd(&op[col + 1],
                              pr * (acc[im][in][half * 2 + 1] * WINV + bb[col + 1]));
                }
            }
        }
    }
}

// ---------------- launch --------------------------------------------------------------
extern "C" void kernel_launch(void* const* d_in, const int* in_sizes, int n_in,
                              void* d_out, int out_size)
{
    (void)in_sizes; (void)n_in; (void)out_size;
    const float* x  = (const float*)d_in[0];
    const float* gw = (const float*)d_in[1];
    const float* w1 = (const float*)d_in[2];
    const float* b1 = (const float*)d_in[3];
    const float* w2 = (const float*)d_in[4];
    const float* b2 = (const float*)d_in[5];
    float* out = (float*)d_out;

    cudaFuncSetAttribute(moe_fp16<DDIM, false>,
                         cudaFuncAttributeMaxDynamicSharedMemorySize, SMEM_BYTES);
    cudaFuncSetAttribute(moe_fp16<FDIM, true>,
                         cudaFuncAttributeMaxDynamicSharedMemorySize, SMEM_BYTES);

    zero_kernel<<<(TOKENS * DDIM + 255) / 256, 256>>>(out, TOKENS * DDIM);
    conv_x_kernel<<<(TOKENS * DDIM / 4 + 255) / 256, 256>>>(
        (const float4*)x, TOKENS * DDIM / 4);
    gate_kernel<<<TOKENS, 256>>>(x, gw);

    dim3 g1(FDIM / BN, TOKENS / BM, NEXP);   // 32 x 32 x 8
    moe_fp16<DDIM, false><<<g1, NTH, SMEM_BYTES>>>(w1, b1, nullptr);

    dim3 g2(DDIM / BN, TOKENS / BM, NEXP);   // 8 x 32 x 8
    moe_fp16<FDIM, true><<<g2, NTH, SMEM_BYTES>>>(w2, b2, out);
}

// round 6
// speedup vs baseline: 5.5513x; 1.4103x over previous
#include <cuda_runtime.h>
#include <cuda_fp16.h>
#include <math.h>
#include <stdint.h>

// ---------------- problem constants -----------------------------------------
#define TOKENS 4096
#define DDIM   1024
#define FDIM   4096
#define NEXP   8
#define PAIRS  (TOKENS * 2)
#define CAP    TOKENS

// ---------------- GEMM tiling ------------------------------------------------
#define BM 128
#define BN 128
#define BK 32
#define NTH 256
#define LDT 40                         // padded smem stride (halves) = 80 B
#define A_BYTES  (BM * LDT * 2)        // 10240
#define STAGE_BYTES (2 * BM * LDT * 2) // A + B = 20480
#define SOFF_STAGE 1024
#define SMEM_BYTES (SOFF_STAGE + 2 * STAGE_BYTES)  // 41984

// ---------------- scratch (72 MB — proven budget) -------------------------------
__device__ int    g_counts[NEXP];
__device__ int    g_list[NEXP * CAP];
__device__ float  g_prob[PAIRS];
__device__ __half g_xf[(size_t)TOKENS * DDIM];   // fp16 x  (8 MB)
__device__ __half g_hf[(size_t)PAIRS * FDIM];    // fp16 h  (64 MB)

// ---------------- ptx helpers --------------------------------------------------
__device__ __forceinline__ uint32_t smem_u32(const void* p) {
    uint32_t a;
    asm("{ .reg .u64 t; cvta.to.shared.u64 t, %1; cvt.u32.u64 %0, t; }"
        : "=r"(a) : "l"(p));
    return a;
}
__device__ __forceinline__ void cp16(uint32_t dst, const void* src) {
    asm volatile("cp.async.cg.shared.global [%0], [%1], 16;" :: "r"(dst), "l"(src));
}
__device__ __forceinline__ void cp_commit() {
    asm volatile("cp.async.commit_group;" ::: "memory");
}
template <int N>
__device__ __forceinline__ void cp_wait() {
    asm volatile("cp.async.wait_group %0;" :: "n"(N) : "memory");
}
__device__ __forceinline__ void ldm4(uint32_t* r, uint32_t a) {
    asm volatile("ldmatrix.sync.aligned.m8n8.x4.shared.b16 {%0,%1,%2,%3}, [%4];"
                 : "=r"(r[0]), "=r"(r[1]), "=r"(r[2]), "=r"(r[3]) : "r"(a));
}
__device__ __forceinline__ void mma_f16(float* c, const uint32_t* a, const uint32_t* b) {
    asm volatile(
        "mma.sync.aligned.m16n8k16.row.col.f32.f16.f16.f32 "
        "{%0,%1,%2,%3}, {%4,%5,%6,%7}, {%8,%9}, {%0,%1,%2,%3};"
        : "+f"(c[0]), "+f"(c[1]), "+f"(c[2]), "+f"(c[3])
        : "r"(a[0]), "r"(a[1]), "r"(a[2]), "r"(a[3]), "r"(b[0]), "r"(b[1]));
}

// ---------------- math helpers --------------------------------------------------
__device__ __forceinline__ float gelu_tanh(float v) {
    const float c = 0.7978845608028654f;
    float u = c * (v + 0.044715f * v * v * v);
    return 0.5f * v * (1.0f + tanhf(u));
}

// convert float4 of W into fp16x4, store 8 B to smem
__device__ __forceinline__ void conv_sts(char* smem, uint32_t off, float4 v) {
    __half2 h0 = __halves2half2(__float2half_rn(v.x), __float2half_rn(v.y));
    __half2 h1 = __halves2half2(__float2half_rn(v.z), __float2half_rn(v.w));
    *reinterpret_cast<uint2*>(smem + off) =
        make_uint2(*(uint32_t*)&h0, *(uint32_t*)&h1);
}

// ---------------- kernel 0: zero output + counts --------------------------------
__global__ void zero_kernel(float* __restrict__ out, int n) {
    int i = blockIdx.x * blockDim.x + threadIdx.x;
    if (i < n) out[i] = 0.0f;
    if (blockIdx.x == 0 && threadIdx.x < NEXP) g_counts[threadIdx.x] = 0;
}

// ---------------- kernel: gate + x->fp16 convert (fused) -------------------------
__global__ __launch_bounds__(256) void gate_kernel(
    const float* __restrict__ x, const float* __restrict__ gw)
{
    int t = blockIdx.x;
    const float* xr = x + (size_t)t * DDIM;

    float acc[NEXP];
#pragma unroll
    for (int e = 0; e < NEXP; e++) acc[e] = 0.0f;
    for (int d = threadIdx.x; d < DDIM; d += 256) {
        float xv = xr[d];
        g_xf[(size_t)t * DDIM + d] = __float2half_rn(xv);   // fused convert
#pragma unroll
        for (int e = 0; e < NEXP; e++) acc[e] += xv * gw[e * DDIM + d];
    }
#pragma unroll
    for (int e = 0; e < NEXP; e++) {
#pragma unroll
        for (int o = 16; o > 0; o >>= 1)
            acc[e] += __shfl_xor_sync(0xffffffff, acc[e], o);
    }
    __shared__ float red[NEXP][8];
    int warp = threadIdx.x >> 5, lane = threadIdx.x & 31;
    if (lane == 0) {
#pragma unroll
        for (int e = 0; e < NEXP; e++) red[e][warp] = acc[e];
    }
    __syncthreads();
    if (threadIdx.x == 0) {
        float lg[NEXP];
#pragma unroll
        for (int e = 0; e < NEXP; e++) {
            float s = 0.0f;
#pragma unroll
            for (int w = 0; w < 8; w++) s += red[e][w];
            lg[e] = s;
        }
        float mx = lg[0];
#pragma unroll
        for (int e = 1; e < NEXP; e++) mx = fmaxf(mx, lg[e]);
        float pe[NEXP], s = 0.0f;
#pragma unroll
        for (int e = 0; e < NEXP; e++) { pe[e] = expf(lg[e] - mx); s += pe[e]; }
        float inv = 1.0f / s;
        int i0 = 0;
#pragma unroll
        for (int e = 1; e < NEXP; e++) if (pe[e] > pe[i0]) i0 = e;
        int i1 = (i0 == 0) ? 1 : 0;
#pragma unroll
        for (int e = 0; e < NEXP; e++)
            if (e != i0 && pe[e] > pe[i1]) i1 = e;
        int p0 = t * 2, p1 = t * 2 + 1;
        g_prob[p0] = pe[i0] * inv;
        g_prob[p1] = pe[i1] * inv;
        int pos0 = atomicAdd(&g_counts[i0], 1);
        g_list[i0 * CAP + pos0] = p0;
        int pos1 = atomicAdd(&g_counts[i1], 1);
        g_list[i1 * CAP + pos1] = p1;
    }
}

// ---------------- grouped single-pass fp16 GEMM ------------------------------------
// C[m,n] = sum_k A[row(m),k] * W[n0+n][k] ; A fp16 via cp.async,
// W fp32 LDG -> fp16 convert -> STS. Double-buffered smem, 1 sync/iter.
template <int KDIM, bool L2TAG>
__global__ __launch_bounds__(NTH, 2)
void moe_fp16(const float* __restrict__ W,
              const float* __restrict__ bias,
              float* __restrict__ dout)
{
    int e   = blockIdx.z;
    int cnt = g_counts[e];
    int m0  = blockIdx.y * BM;
    if (m0 >= cnt) return;
    int n0  = blockIdx.x * BN;

    extern __shared__ __align__(128) char smem[];
    uint32_t sb = smem_u32(smem);
    int* rows = (int*)smem;

    int tid = threadIdx.x, wid = tid >> 5, lane = tid & 31;

    if (tid < BM) {
        int m = m0 + tid;
        rows[tid] = g_list[e * CAP + (m < cnt ? m : m0)];
    }
    __syncthreads();

    // ---- A: cp.async mapping (2 x 16B per thread) ----
    int arow = tid >> 1;
    int pa = rows[arow];
    const __half* a_row = L2TAG ? (g_hf + (size_t)pa * KDIM)
                                : (g_xf + (size_t)(pa >> 1) * KDIM);
    const char* a_src = (const char*)a_row + (tid & 1) * 32;
    uint32_t a_dst = sb + SOFF_STAGE + (uint32_t)arow * 80 + (tid & 1) * 32;

    // ---- W: LDG float4 mapping (4 per thread) ----
    const float* wp[4];
    uint32_t woff[4];
#pragma unroll
    for (int j = 0; j < 4; j++) {
        int s = tid + j * 256;
        int r = s >> 3;
        int k4 = (s & 7) << 2;
        wp[j] = W + ((size_t)(n0 + r) * NEXP + e) * KDIM + k4;
        woff[j] = (uint32_t)r * 80 + (uint32_t)k4 * 2;
    }

    constexpr int NCH = KDIM / BK;

    // ---- fragment addressing (validated in R2/R5) ----
    int wm = wid & 1, wn = wid >> 1;
    int li = lane >> 3, lr = lane & 7;
    uint32_t aoff = (uint32_t)((wm * 64 + lr + (li & 1) * 8) * 80 + (li >> 1) * 16);
    uint32_t boff = (uint32_t)((wn * 32 + (li >> 1) * 8 + lr) * 80 + (li & 1) * 16);

    float acc[4][4][4];
#pragma unroll
    for (int im = 0; im < 4; im++)
#pragma unroll
        for (int in = 0; in < 4; in++)
#pragma unroll
            for (int q = 0; q < 4; q++) acc[im][in][q] = 0.0f;

    // ---- prologue: A chunk0 in flight, W chunk0 in regs ----
    cp16(a_dst, a_src);
    cp16(a_dst + 16, a_src + 16);
    cp_commit();
    float4 wreg[4];
#pragma unroll
    for (int j = 0; j < 4; j++) wreg[j] = *(const float4*)(wp[j]);

    for (int i = 0; i < NCH; i++) {
        uint32_t st = sb + SOFF_STAGE + (uint32_t)(i & 1) * STAGE_BYTES;
        char* stc = smem + SOFF_STAGE + (size_t)(i & 1) * STAGE_BYTES;

        // stage W chunk i (fp32 -> fp16)
#pragma unroll
        for (int j = 0; j < 4; j++)
            conv_sts(stc, A_BYTES + woff[j], wreg[j]);

        cp_wait<0>();          // A chunk i landed
        __syncthreads();       // all staging visible; prior buffer reads done

        // issue A chunk i+1 into the other buffer
        if (i + 1 < NCH) {
            uint32_t nst = sb + SOFF_STAGE + (uint32_t)((i + 1) & 1) * STAGE_BYTES
                         + (a_dst - (sb + SOFF_STAGE));
            int kb = (i + 1) * BK * 2;
            cp16(nst, a_src + kb);
            cp16(nst + 16, a_src + kb + 16);
        }
        cp_commit();

        // prefetch W chunk i+1
        if (i + 1 < NCH) {
            int k0 = (i + 1) * BK;
#pragma unroll
            for (int j = 0; j < 4; j++) wreg[j] = *(const float4*)(wp[j] + k0);
        }

        // compute chunk i
        uint32_t As = st, Bs = st + A_BYTES;
#pragma unroll
        for (int kk = 0; kk < BK; kk += 16) {
            uint32_t bf[4][2];
#pragma unroll
            for (int h = 0; h < 2; h++) {
                uint32_t t4[4];
                ldm4(t4, Bs + boff + h * 1280 + kk * 2);
                bf[2 * h][0] = t4[0]; bf[2 * h][1] = t4[1];
                bf[2 * h + 1][0] = t4[2]; bf[2 * h + 1][1] = t4[3];
            }
#pragma unroll
            for (int im = 0; im < 4; im++) {
                uint32_t af[4];
                ldm4(af, As + aoff + im * 1280 + kk * 2);
#pragma unroll
                for (int in = 0; in < 4; in++)
                    mma_f16(acc[im][in], af, bf[in]);
            }
        }
    }

    // ---- epilogue ----
    int qr = lane >> 2, qc = (lane & 3) * 2;
#pragma unroll
    for (int im = 0; im < 4; im++) {
#pragma unroll
        for (int half = 0; half < 2; half++) {
            int m_loc = wm * 64 + im * 16 + qr + half * 8;
            if (m0 + m_loc >= cnt) continue;
            int p = rows[m_loc];
            if (!L2TAG) {
                __half* hp = g_hf + (size_t)p * FDIM;
                const float* bb = bias + (size_t)e * FDIM;
#pragma unroll
                for (int in = 0; in < 4; in++) {
                    int col = n0 + wn * 32 + in * 8 + qc;
                    float v0 = acc[im][in][half * 2 + 0] + bb[col];
                    float v1 = acc[im][in][half * 2 + 1] + bb[col + 1];
                    __half2 hv = __halves2half2(__float2half_rn(gelu_tanh(v0)),
                                                __float2half_rn(gelu_tanh(v1)));
                    *reinterpret_cast<uint32_t*>(hp + col) = *(uint32_t*)&hv;
                }
            } else {
                float pr = g_prob[p];
                float* op = dout + (size_t)(p >> 1) * DDIM;
                const float* bb = bias + (size_t)e * DDIM;
#pragma unroll
                for (int in = 0; in < 4; in++) {
                    int col = n0 + wn * 32 + in * 8 + qc;
                    atomicAdd(&op[col],
                              pr * (acc[im][in][half * 2 + 0] + bb[col]));
                    atomicAdd(&op[col + 1],
                              pr * (acc[im][in][half * 2 + 1] + bb[col + 1]));
                }
            }
        }
    }
}

// ---------------- launch --------------------------------------------------------------
extern "C" void kernel_launch(void* const* d_in, const int* in_sizes, int n_in,
                              void* d_out, int out_size)
{
    (void)in_sizes; (void)n_in; (void)out_size;
    const float* x  = (const float*)d_in[0];
    const float* gw = (const float*)d_in[1];
    const float* w1 = (const float*)d_in[2];
    const float* b1 = (const float*)d_in[3];
    const float* w2 = (const float*)d_in[4];
    const float* b2 = (const float*)d_in[5];
    float* out = (float*)d_out;

    cudaFuncSetAttribute(moe_fp16<DDIM, false>,
                         cudaFuncAttributeMaxDynamicSharedMemorySize, SMEM_BYTES);
    cudaFuncSetAttribute(moe_fp16<FDIM, true>,
                         cudaFuncAttributeMaxDynamicSharedMemorySize, SMEM_BYTES);

    zero_kernel<<<(TOKENS * DDIM + 255) / 256, 256>>>(out, TOKENS * DDIM);
    gate_kernel<<<TOKENS, 256>>>(x, gw);

    dim3 g1(FDIM / BN, TOKENS / BM, NEXP);   // 32 x 32 x 8
    moe_fp16<DDIM, false><<<g1, NTH, SMEM_BYTES>>>(w1, b1, nullptr);

    dim3 g2(DDIM / BN, TOKENS / BM, NEXP);   // 8 x 32 x 8
    moe_fp16<FDIM, true><<<g2, NTH, SMEM_BYTES>>>(w2, b2, out);
}